// round 14
// baseline (speedup 1.0000x reference)
#include <cuda_runtime.h>
#include <cuda_bf16.h>
#include <math_constants.h>

#define N_STATES   65536
#define LATENT     512
#define NCOL       (LATENT / 4)           // 128 float4 columns
#define OCC        3
#define NBLK       (148 * OCC)            // 444 blocks, ALL resident (enforced)
#define WARPS_PB   8
#define NWARP      (NBLK * WARPS_PB)      // 3552 warps
#define INF_BITS   0x7F800000

// balanced contiguous spans: warp gw owns rows [span(gw), span(gw+1))
// span(gw) = 18*gw + floor(50*gw/111)   (50/111 == 1600/3552 extra rows)
// -> every warp gets 18 or 19 rows, 19-row warps spread uniformly over SMs
__device__ __forceinline__ int span_start(int gw) {
    return 18 * gw + (50 * gw) / 111;
}

// ---- static scratch (no allocation allowed) ----
__device__ float              g_blk_Z[NBLK];
__device__ float              g_blk_m[NBLK];
__device__ float              g_blk_q[NBLK * LATENT];  // ~909 KB, L2-hot at combine time
__device__ int                g_gmin_bits = INF_BITS;  // atomicMin'd float bits (dists>=0)
__device__ unsigned long long g_sync = 0ULL;           // monotonic grid-sync ticket
__device__ unsigned           g_ctr  = 0;              // loss completion ticket (self-reset)

__device__ __forceinline__ unsigned long long ld_acq_u64(const unsigned long long* p) {
    unsigned long long v;
    asm volatile("ld.global.acquire.gpu.u64 %0, [%1];" : "=l"(v) : "l"(p));
    return v;
}
// volatile LDS.128 — keeps the input-stats replica in shared memory instead of regs
__device__ __forceinline__ float4 lds128v(const float4* smem_ptr) {
    float4 r;
    unsigned addr = (unsigned)__cvta_generic_to_shared(smem_ptr);
    asm volatile("ld.volatile.shared.v4.f32 {%0,%1,%2,%3}, [%4];"
                 : "=f"(r.x), "=f"(r.y), "=f"(r.z), "=f"(r.w) : "r"(addr));
    return r;
}

// phase-overlaid shared memory: per-warp mu stash (phase 1) vs fold/combine scratch
union SmemU {
    float2 stage[WARPS_PB][8][32];        // 16 KB: row-n mus parked during prefetch of n+1
    struct {
        float  q[WARPS_PB][LATENT];       // 16 KB: warp partial fold
        float4 cv[8];                     // combine: 8 warp-partial float4s
        float  red[8];                    // combine: 8 warp-partial scalars
    } fold;
};

// ======================================================================
// Single fused persistent kernel, occupancy 3 (24 warps/SM):
//   phase 1: warp-per-row streaming over BALANCED contiguous spans
//            (442-443 rows per SM, 0.2% spread); row n's mus parked in
//            smem so row n+1's 8 LDG.128 fly during the shuffle/exp/
//            q-update serial chain; first loads issued before setup
//   grid sync (monotonic ticket; all blocks resident); global min via
//   atomicMin on float bits (true min -> deterministic, replay-safe reset)
//   phase 2: blocks 0..127 fold one float4 column each; rescale factors
//            registerized, all reductions warp-shuffle based (3 syncs)
// ======================================================================
__global__ __launch_bounds__(256, OCC)
void quant_fused(const float* __restrict__ imu,
                 const float* __restrict__ isg,
                 const float4* __restrict__ onst,   // row = 256 float4
                 float* __restrict__ out)           // [512 | 1 | 1 | 65536]
{
    __shared__ SmemU              u;                       // 20 KB
    __shared__ float4             s_a[8 * 32];             //  4 KB input stats [k*32+lane]
    __shared__ float              s_m[WARPS_PB];
    __shared__ float              s_Z[WARPS_PB];
    __shared__ unsigned long long s_epoch;
    __shared__ int                c_last;

    const int lane = threadIdx.x & 31;
    const int wid  = threadIdx.x >> 5;
    const int t    = threadIdx.x;
    const int gw   = blockIdx.x * WARPS_PB + wid;
    float* dists_out = out + LATENT + 2;

    const int rbeg = span_start(gw);
    const int rend = span_start(gw + 1);   // 18 or 19 rows, contiguous

    // (0) FIRST: get the opening DRAM requests in flight
    float4 v[8];
    {
        const float4* p = onst + (size_t)rbeg * 256 + lane;
#pragma unroll
        for (int k = 0; k < 8; k++) v[k] = __ldcs(p + 32 * k);
    }

    // per-lane input-stats replica in shared (saves 32 regs):
    // entry [k*32+lane] covers float4 j=lane+32k -> d=2j (x:mu,y:sig), d=2j+1 (z:mu,w:sig)
    {
        int k2 = t >> 5, l2 = t & 31;
        int d0 = 2 * (l2 + 32 * k2);
        s_a[k2 * 32 + l2] = make_float4(imu[d0], isg[d0], imu[d0 + 1], isg[d0 + 1]);
    }
    __syncthreads();

    float m = CUDART_INF_F;
    float Z = 0.f;
    float q[16];
#pragma unroll
    for (int i = 0; i < 16; i++) q[i] = 0.f;

    // ---------------- phase 1: mu-stash pipelined streaming ----------------
    for (int row = rbeg; row < rend; row++) {
        // (1) consume v: dist partial + park mus in the per-warp smem stash
        float s = 0.f;
#pragma unroll
        for (int k = 0; k < 8; k++) {
            float4 vk = v[k];
            float4 ak = lds128v(&s_a[k * 32 + lane]);
            u.stage[wid][k][lane] = make_float2(vk.x, vk.z);
            float dx = vk.x - ak.x; s = fmaf(dx, dx, s);
            float dy = vk.y - ak.y; s = fmaf(dy, dy, s);
            float dz = vk.z - ak.z; s = fmaf(dz, dz, s);
            float dw = vk.w - ak.w; s = fmaf(dw, dw, s);
        }

        // (2) v is dead: immediately launch next row's loads into it
        if (row + 1 < rend) {
            const float4* pn = onst + (size_t)(row + 1) * 256 + lane;
#pragma unroll
            for (int k = 0; k < 8; k++) v[k] = __ldcs(pn + 32 * k);
        }

        // (3) serial chain runs while the 8 LDG.128 are in flight
#pragma unroll
        for (int o = 16; o > 0; o >>= 1)
            s += __shfl_xor_sync(0xffffffffu, s, o);

        if (lane == 0) dists_out[row] = s;

        // online softmin: weights exp(m - d_i), m = running min
        float w;
        if (s < m) {
            float f = __expf(s - m);       // first row: exp(-inf) = 0
            Z *= f;
#pragma unroll
            for (int i = 0; i < 16; i++) q[i] *= f;
            m = s;
            w = 1.f;
        } else {
            w = __expf(m - s);
        }
        Z += w;

        // (4) q-update from the stash (LDS, not the overwritten v)
#pragma unroll
        for (int k = 0; k < 8; k++) {
            float2 mu = u.stage[wid][k][lane];
            q[2 * k]     = fmaf(w, mu.x, q[2 * k]);
            q[2 * k + 1] = fmaf(w, mu.y, q[2 * k + 1]);
        }
    }

    // ---- in-block fold of 8 warp states -> one (m, Z, q[512]) partial ----
    if (lane == 0) s_m[wid] = m;
    __syncthreads();                       // all warps done with u.stage

    float mB = s_m[0];
#pragma unroll
    for (int w2 = 1; w2 < WARPS_PB; w2++) mB = fminf(mB, s_m[w2]);

    const float fw = __expf(mB - m);       // <= 1
    if (lane == 0) s_Z[wid] = Z * fw;
#pragma unroll
    for (int k = 0; k < 8; k++) {
        int j = lane + 32 * k;
        u.fold.q[wid][2 * j]     = q[2 * k]     * fw;
        u.fold.q[wid][2 * j + 1] = q[2 * k + 1] * fw;
    }
    __syncthreads();

#pragma unroll
    for (int h = 0; h < 2; h++) {
        int c = t + 256 * h;
        float acc = 0.f;
#pragma unroll
        for (int w2 = 0; w2 < WARPS_PB; w2++) acc += u.fold.q[w2][c];
        g_blk_q[blockIdx.x * LATENT + c] = acc;
    }
    if (t == 0) {
        float zz = 0.f;
#pragma unroll
        for (int w2 = 0; w2 < WARPS_PB; w2++) zz += s_Z[w2];
        g_blk_Z[blockIdx.x] = zz;
        g_blk_m[blockIdx.x] = mB;
        // dists >= 0 -> float bits compare correctly as signed ints
        atomicMin(&g_gmin_bits, __float_as_int(mB));
    }

    // ---------------- grid sync (monotonic, graph-replay safe) ----------------
    __threadfence();
    if (t == 0) {
        unsigned long long ticket = atomicAdd(&g_sync, 1ULL);
        s_epoch = ticket / NBLK;           // same value for all blocks this launch
    }
    __syncthreads();

    if (blockIdx.x >= NCOL) return;        // non-combining blocks done

    if (t == 0) {
        const unsigned long long target = (s_epoch + 1ULL) * NBLK;
        while (ld_acq_u64(&g_sync) < target) { }
    }
    __syncthreads();
    __threadfence();                        // acquire partials from all blocks

    // ---------------- phase 2: column-parallel combine (L2-hot) ----------------
    // thread t handles partials b0=t and b1=t+256 (b1 valid iff t < NBLK-256);
    // rescale factors stay in registers, reductions are warp-shuffle based.
    const int j = blockIdx.x;              // float4 column 0..127
    const float M = __int_as_float(__ldcg(&g_gmin_bits));   // true global min
    const int b0 = t, b1 = t + 256;
    const bool has1 = (b1 < NBLK);
    const float4* q4 = (const float4*)g_blk_q;

    // issue both column loads early so L2 latency overlaps the Z reduction
    float4 x0 = q4[(size_t)b0 * NCOL + j];
    float4 x1 = has1 ? q4[(size_t)b1 * NCOL + j] : make_float4(0.f, 0.f, 0.f, 0.f);

    float fb0 = __expf(M - g_blk_m[b0]);
    float fb1 = has1 ? __expf(M - g_blk_m[b1]) : 0.f;

    float zv = g_blk_Z[b0] * fb0;
    if (has1) zv = fmaf(g_blk_Z[b1], fb1, zv);
#pragma unroll
    for (int o = 16; o > 0; o >>= 1)
        zv += __shfl_xor_sync(0xffffffffu, zv, o);
    if (lane == 0) u.fold.red[wid] = zv;

    // per-thread column fold, then warp-shuffle float4 reduce
    float4 acc;
    acc.x = fmaf(fb1, x1.x, fb0 * x0.x);
    acc.y = fmaf(fb1, x1.y, fb0 * x0.y);
    acc.z = fmaf(fb1, x1.z, fb0 * x0.z);
    acc.w = fmaf(fb1, x1.w, fb0 * x0.w);
#pragma unroll
    for (int o = 16; o > 0; o >>= 1) {
        acc.x += __shfl_xor_sync(0xffffffffu, acc.x, o);
        acc.y += __shfl_xor_sync(0xffffffffu, acc.y, o);
        acc.z += __shfl_xor_sync(0xffffffffu, acc.z, o);
        acc.w += __shfl_xor_sync(0xffffffffu, acc.w, o);
    }
    if (lane == 0) u.fold.cv[wid] = acc;
    __syncthreads();

    if (t == 0) {
        float Z2 = 0.f;
#pragma unroll
        for (int w2 = 0; w2 < WARPS_PB; w2++) Z2 += u.fold.red[w2];
        float4 r = u.fold.cv[0];
#pragma unroll
        for (int w2 = 1; w2 < WARPS_PB; w2++) {
            float4 x = u.fold.cv[w2];
            r.x += x.x; r.y += x.y; r.z += x.z; r.w += x.w;
        }
        ((float4*)out)[j] = make_float4(r.x / Z2, r.y / Z2, r.z / Z2, r.w / Z2);
    }

    // ---- last-block-done: losses from the finalized quantised vector ----
    __threadfence();
    if (t == 0) c_last = (atomicAdd(&g_ctr, 1u) == NCOL - 1);
    __syncthreads();

    if (c_last) {
        __threadfence();                   // acquire other blocks' out[] writes
        float e = 0.f;
        for (int d = t; d < LATENT; d += 256) {
            float qd   = __ldcg(&out[d]);  // bypass L1: other SMs wrote these
            float diff = qd - imu[d];
            e = fmaf(diff, diff, e);
        }
#pragma unroll
        for (int o = 16; o > 0; o >>= 1)
            e += __shfl_xor_sync(0xffffffffu, e, o);
        if (lane == 0) u.fold.red[wid] = e;
        __syncthreads();
        if (t == 0) {
            float ssum = 0.f;
#pragma unroll
            for (int w2 = 0; w2 < WARPS_PB; w2++) ssum += u.fold.red[w2];
            float loss = ssum / (float)LATENT;
            out[LATENT]     = loss;   // loss_enc
            out[LATENT + 1] = loss;   // loss_ref (stop_gradient => same value)
            g_ctr = 0;                // reset for next graph replay
            g_gmin_bits = INF_BITS;   // reset for next graph replay
        }
    }
}

// ======================================================================
extern "C" void kernel_launch(void* const* d_in, const int* in_sizes, int n_in,
                              void* d_out, int out_size)
{
    const float*  imu  = (const float*)d_in[0];   // input_mu  [512]
    const float*  isg  = (const float*)d_in[1];   // input_sig [512]
    const float4* onst = (const float4*)d_in[2];  // on_states [65536,512,2]
    float* out = (float*)d_out;                   // [512 | 1 | 1 | 65536]

    quant_fused<<<NBLK, 256>>>(imu, isg, onst, out);
}

// round 15
// speedup vs baseline: 1.0374x; 1.0374x over previous
#include <cuda_runtime.h>
#include <cuda_bf16.h>
#include <math_constants.h>

#define N_STATES   65536
#define LATENT     512
#define NCOL       (LATENT / 4)           // 128 float4 columns
#define OCC        3
#define NBLK       (148 * OCC)            // 444 blocks, ALL resident (enforced)
#define WARPS_PB   8
#define NWARP      (NBLK * WARPS_PB)      // 3552 warps
#define BASE_ROWS  18                     // 18*3552 = 63936 rows via grid-stride
#define TAIL_BASE  (BASE_ROWS * NWARP)    // rows 63936..65535 = 1600 tail rows
#define INF_BITS   0x7F800000

// ---- static scratch (no allocation allowed) ----
__device__ float              g_blk_Z[NBLK];
__device__ float              g_blk_m[NBLK];
__device__ float              g_blk_q[NBLK * LATENT];  // ~909 KB, L2-hot at combine time
__device__ int                g_gmin_bits = INF_BITS;  // atomicMin'd float bits (dists>=0)
__device__ unsigned long long g_sync = 0ULL;           // monotonic grid-sync ticket
__device__ unsigned           g_ctr  = 0;              // loss completion ticket (self-reset)

__device__ __forceinline__ unsigned long long ld_acq_u64(const unsigned long long* p) {
    unsigned long long v;
    asm volatile("ld.global.acquire.gpu.u64 %0, [%1];" : "=l"(v) : "l"(p));
    return v;
}
// volatile LDS.128 — keeps the input-stats replica in shared memory instead of regs
__device__ __forceinline__ float4 lds128v(const float4* smem_ptr) {
    float4 r;
    unsigned addr = (unsigned)__cvta_generic_to_shared(smem_ptr);
    asm volatile("ld.volatile.shared.v4.f32 {%0,%1,%2,%3}, [%4];"
                 : "=f"(r.x), "=f"(r.y), "=f"(r.z), "=f"(r.w) : "r"(addr));
    return r;
}

// phase-overlaid shared memory: per-warp mu stash (phase 1) vs fold/combine scratch
union SmemU {
    float2 stage[WARPS_PB][8][32];        // 16 KB: row-n mus parked during prefetch of n+1
    struct {
        float  q[WARPS_PB][LATENT];       // 16 KB: warp partial fold
        float4 cv[8];                     // combine: 8 warp-partial float4s
        float  red[8];                    // combine: 8 warp-partial scalars
    } fold;
};

// ======================================================================
// Single fused persistent kernel, occupancy 3 (24 warps/SM):
//   phase 1: R13's interleaved grid-stride for 18 rows/warp (measured-best
//            access pattern), plus 1600 tail rows handed one-per-heavy-warp
//            with heavy warps spread UNIFORMLY over blocks (3-4 per block,
//            442-443 rows/SM -> 0.2% imbalance instead of 5.5%);
//            row n's mus parked in smem so row n+1's 8 LDG.128 fly during
//            the shuffle/exp/q-update serial chain
//   grid sync (monotonic ticket; all blocks resident); global min via
//   atomicMin on float bits (true min -> deterministic, replay-safe reset)
//   phase 2: blocks 0..127 fold one float4 column each; rescale factors
//            registerized, all reductions warp-shuffle based (3 syncs)
// ======================================================================
__global__ __launch_bounds__(256, OCC)
void quant_fused(const float* __restrict__ imu,
                 const float* __restrict__ isg,
                 const float4* __restrict__ onst,   // row = 256 float4
                 float* __restrict__ out)           // [512 | 1 | 1 | 65536]
{
    __shared__ SmemU              u;                       // 20 KB
    __shared__ float4             s_a[8 * 32];             //  4 KB input stats [k*32+lane]
    __shared__ float              s_m[WARPS_PB];
    __shared__ float              s_Z[WARPS_PB];
    __shared__ unsigned long long s_epoch;
    __shared__ int                c_last;

    const int lane = threadIdx.x & 31;
    const int wid  = threadIdx.x >> 5;
    const int t    = threadIdx.x;
    const int gw   = blockIdx.x * WARPS_PB + wid;
    float* dists_out = out + LATENT + 2;

    // uniform tail distribution: warp gw is "heavy" (gets one tail row) iff
    // floor((gw+1)*1600/3552) > floor(gw*1600/3552); its tail row is
    // TAIL_BASE + floor(gw*1600/3552). Exactly 1600 heavy warps, 3-4/block.
    const int hr     = (gw * 1600) / NWARP;
    const int nrows  = BASE_ROWS + (((gw + 1) * 1600) / NWARP > hr);
    const int tailrw = TAIL_BASE + hr;

    // (0) FIRST: get the opening DRAM requests in flight (row k=0 is gw)
    float4 v[8];
    {
        const float4* p = onst + (size_t)gw * 256 + lane;
#pragma unroll
        for (int k = 0; k < 8; k++) v[k] = __ldcs(p + 32 * k);
    }

    // per-lane input-stats replica in shared (saves 32 regs):
    // entry [k*32+lane] covers float4 j=lane+32k -> d=2j (x:mu,y:sig), d=2j+1 (z:mu,w:sig)
    {
        int k2 = t >> 5, l2 = t & 31;
        int d0 = 2 * (l2 + 32 * k2);
        s_a[k2 * 32 + l2] = make_float4(imu[d0], isg[d0], imu[d0 + 1], isg[d0 + 1]);
    }
    __syncthreads();

    float m = CUDART_INF_F;
    float Z = 0.f;
    float q[16];
#pragma unroll
    for (int i = 0; i < 16; i++) q[i] = 0.f;

    // ---------------- phase 1: mu-stash pipelined streaming ----------------
    int row = gw;                          // row for iteration k: gw + k*NWARP, then tailrw
    for (int k = 0; k < nrows; k++) {
        // (1) consume v: dist partial + park mus in the per-warp smem stash
        float s = 0.f;
#pragma unroll
        for (int kk = 0; kk < 8; kk++) {
            float4 vk = v[kk];
            float4 ak = lds128v(&s_a[kk * 32 + lane]);
            u.stage[wid][kk][lane] = make_float2(vk.x, vk.z);
            float dx = vk.x - ak.x; s = fmaf(dx, dx, s);
            float dy = vk.y - ak.y; s = fmaf(dy, dy, s);
            float dz = vk.z - ak.z; s = fmaf(dz, dz, s);
            float dw = vk.w - ak.w; s = fmaf(dw, dw, s);
        }

        // (2) v is dead: immediately launch next row's loads into it
        const int kn = k + 1;
        if (kn < nrows) {
            const int nrow = (kn < BASE_ROWS) ? gw + kn * NWARP : tailrw;
            const float4* pn = onst + (size_t)nrow * 256 + lane;
#pragma unroll
            for (int kk = 0; kk < 8; kk++) v[kk] = __ldcs(pn + 32 * kk);
        }

        // (3) serial chain runs while the 8 LDG.128 are in flight
#pragma unroll
        for (int o = 16; o > 0; o >>= 1)
            s += __shfl_xor_sync(0xffffffffu, s, o);

        if (lane == 0) dists_out[row] = s;

        // online softmin: weights exp(m - d_i), m = running min
        float w;
        if (s < m) {
            float f = __expf(s - m);       // first row: exp(-inf) = 0
            Z *= f;
#pragma unroll
            for (int i = 0; i < 16; i++) q[i] *= f;
            m = s;
            w = 1.f;
        } else {
            w = __expf(m - s);
        }
        Z += w;

        // (4) q-update from the stash (LDS, not the overwritten v)
#pragma unroll
        for (int kk = 0; kk < 8; kk++) {
            float2 mu = u.stage[wid][kk][lane];
            q[2 * kk]     = fmaf(w, mu.x, q[2 * kk]);
            q[2 * kk + 1] = fmaf(w, mu.y, q[2 * kk + 1]);
        }

        row = (kn < BASE_ROWS) ? gw + kn * NWARP : tailrw;
    }

    // ---- in-block fold of 8 warp states -> one (m, Z, q[512]) partial ----
    if (lane == 0) s_m[wid] = m;
    __syncthreads();                       // all warps done with u.stage

    float mB = s_m[0];
#pragma unroll
    for (int w2 = 1; w2 < WARPS_PB; w2++) mB = fminf(mB, s_m[w2]);

    const float fw = __expf(mB - m);       // <= 1
    if (lane == 0) s_Z[wid] = Z * fw;
#pragma unroll
    for (int k = 0; k < 8; k++) {
        int j = lane + 32 * k;
        u.fold.q[wid][2 * j]     = q[2 * k]     * fw;
        u.fold.q[wid][2 * j + 1] = q[2 * k + 1] * fw;
    }
    __syncthreads();

#pragma unroll
    for (int h = 0; h < 2; h++) {
        int c = t + 256 * h;
        float acc = 0.f;
#pragma unroll
        for (int w2 = 0; w2 < WARPS_PB; w2++) acc += u.fold.q[w2][c];
        g_blk_q[blockIdx.x * LATENT + c] = acc;
    }
    if (t == 0) {
        float zz = 0.f;
#pragma unroll
        for (int w2 = 0; w2 < WARPS_PB; w2++) zz += s_Z[w2];
        g_blk_Z[blockIdx.x] = zz;
        g_blk_m[blockIdx.x] = mB;
        // dists >= 0 -> float bits compare correctly as signed ints
        atomicMin(&g_gmin_bits, __float_as_int(mB));
    }

    // ---------------- grid sync (monotonic, graph-replay safe) ----------------
    __threadfence();
    if (t == 0) {
        unsigned long long ticket = atomicAdd(&g_sync, 1ULL);
        s_epoch = ticket / NBLK;           // same value for all blocks this launch
    }
    __syncthreads();

    if (blockIdx.x >= NCOL) return;        // non-combining blocks done

    if (t == 0) {
        const unsigned long long target = (s_epoch + 1ULL) * NBLK;
        while (ld_acq_u64(&g_sync) < target) { }
    }
    __syncthreads();
    __threadfence();                        // acquire partials from all blocks

    // ---------------- phase 2: column-parallel combine (L2-hot) ----------------
    // thread t handles partials b0=t and b1=t+256 (b1 valid iff t < NBLK-256);
    // rescale factors stay in registers, reductions are warp-shuffle based.
    const int j = blockIdx.x;              // float4 column 0..127
    const float M = __int_as_float(__ldcg(&g_gmin_bits));   // true global min
    const int b0 = t, b1 = t + 256;
    const bool has1 = (b1 < NBLK);
    const float4* q4 = (const float4*)g_blk_q;

    // issue both column loads early so L2 latency overlaps the Z reduction
    float4 x0 = q4[(size_t)b0 * NCOL + j];
    float4 x1 = has1 ? q4[(size_t)b1 * NCOL + j] : make_float4(0.f, 0.f, 0.f, 0.f);

    float fb0 = __expf(M - g_blk_m[b0]);
    float fb1 = has1 ? __expf(M - g_blk_m[b1]) : 0.f;

    float zv = g_blk_Z[b0] * fb0;
    if (has1) zv = fmaf(g_blk_Z[b1], fb1, zv);
#pragma unroll
    for (int o = 16; o > 0; o >>= 1)
        zv += __shfl_xor_sync(0xffffffffu, zv, o);
    if (lane == 0) u.fold.red[wid] = zv;

    // per-thread column fold, then warp-shuffle float4 reduce
    float4 acc;
    acc.x = fmaf(fb1, x1.x, fb0 * x0.x);
    acc.y = fmaf(fb1, x1.y, fb0 * x0.y);
    acc.z = fmaf(fb1, x1.z, fb0 * x0.z);
    acc.w = fmaf(fb1, x1.w, fb0 * x0.w);
#pragma unroll
    for (int o = 16; o > 0; o >>= 1) {
        acc.x += __shfl_xor_sync(0xffffffffu, acc.x, o);
        acc.y += __shfl_xor_sync(0xffffffffu, acc.y, o);
        acc.z += __shfl_xor_sync(0xffffffffu, acc.z, o);
        acc.w += __shfl_xor_sync(0xffffffffu, acc.w, o);
    }
    if (lane == 0) u.fold.cv[wid] = acc;
    __syncthreads();

    if (t == 0) {
        float Z2 = 0.f;
#pragma unroll
        for (int w2 = 0; w2 < WARPS_PB; w2++) Z2 += u.fold.red[w2];
        float4 r = u.fold.cv[0];
#pragma unroll
        for (int w2 = 1; w2 < WARPS_PB; w2++) {
            float4 x = u.fold.cv[w2];
            r.x += x.x; r.y += x.y; r.z += x.z; r.w += x.w;
        }
        ((float4*)out)[j] = make_float4(r.x / Z2, r.y / Z2, r.z / Z2, r.w / Z2);
    }

    // ---- last-block-done: losses from the finalized quantised vector ----
    __threadfence();
    if (t == 0) c_last = (atomicAdd(&g_ctr, 1u) == NCOL - 1);
    __syncthreads();

    if (c_last) {
        __threadfence();                   // acquire other blocks' out[] writes
        float e = 0.f;
        for (int d = t; d < LATENT; d += 256) {
            float qd   = __ldcg(&out[d]);  // bypass L1: other SMs wrote these
            float diff = qd - imu[d];
            e = fmaf(diff, diff, e);
        }
#pragma unroll
        for (int o = 16; o > 0; o >>= 1)
            e += __shfl_xor_sync(0xffffffffu, e, o);
        if (lane == 0) u.fold.red[wid] = e;
        __syncthreads();
        if (t == 0) {
            float ssum = 0.f;
#pragma unroll
            for (int w2 = 0; w2 < WARPS_PB; w2++) ssum += u.fold.red[w2];
            float loss = ssum / (float)LATENT;
            out[LATENT]     = loss;   // loss_enc
            out[LATENT + 1] = loss;   // loss_ref (stop_gradient => same value)
            g_ctr = 0;                // reset for next graph replay
            g_gmin_bits = INF_BITS;   // reset for next graph replay
        }
    }
}

// ======================================================================
extern "C" void kernel_launch(void* const* d_in, const int* in_sizes, int n_in,
                              void* d_out, int out_size)
{
    const float*  imu  = (const float*)d_in[0];   // input_mu  [512]
    const float*  isg  = (const float*)d_in[1];   // input_sig [512]
    const float4* onst = (const float4*)d_in[2];  // on_states [65536,512,2]
    float* out = (float*)d_out;                   // [512 | 1 | 1 | 65536]

    quant_fused<<<NBLK, 256>>>(imu, isg, onst, out);
}

// round 17
// speedup vs baseline: 1.0437x; 1.0061x over previous
#include <cuda_runtime.h>
#include <cuda_bf16.h>
#include <math_constants.h>

#define N_STATES   65536
#define LATENT     512
#define NCOL       (LATENT / 4)           // 128 float4 columns
#define OCC        3
#define NBLK       (148 * OCC)            // 444 blocks, ALL resident (enforced)
#define WARPS_PB   8
#define NWARP      (NBLK * WARPS_PB)      // 3552 warps
#define BASE_ROWS  18                     // 18*3552 = 63936 rows via grid-stride
#define TAIL_BASE  (BASE_ROWS * NWARP)    // rows 63936..65535 = 1600 tail rows
#define INF_BITS   0x7F800000

// ---- static scratch (no allocation allowed) ----
__device__ float              g_blk_Z[NBLK];
__device__ float              g_blk_m[NBLK];
__device__ float              g_blk_q[NBLK * LATENT];  // ~909 KB, L2-hot at combine time
__device__ int                g_gmin_bits = INF_BITS;  // atomicMin'd float bits (dists>=0)
__device__ unsigned long long g_sync = 0ULL;           // monotonic grid-sync ticket
__device__ unsigned           g_ctr  = 0;              // loss completion ticket (self-reset)

__device__ __forceinline__ unsigned long long ld_acq_u64(const unsigned long long* p) {
    unsigned long long v;
    asm volatile("ld.global.acquire.gpu.u64 %0, [%1];" : "=l"(v) : "l"(p));
    return v;
}
// volatile LDS.128 — keeps the input-stats replica in shared memory instead of regs
__device__ __forceinline__ float4 lds128v(const float4* smem_ptr) {
    float4 r;
    unsigned addr = (unsigned)__cvta_generic_to_shared(smem_ptr);
    asm volatile("ld.volatile.shared.v4.f32 {%0,%1,%2,%3}, [%4];"
                 : "=f"(r.x), "=f"(r.y), "=f"(r.z), "=f"(r.w) : "r"(addr));
    return r;
}

// phase-overlaid shared memory: per-warp mu stash (phase 1) vs fold/combine scratch
union SmemU {
    float2 stage[WARPS_PB][8][32];        // 16 KB: row-n mus parked during prefetch of n+1
    struct {
        float  q[WARPS_PB][LATENT];       // 16 KB: warp partial fold
        float4 cv[8];                     // combine: 8 warp-partial float4s
        float  red[8];                    // combine: 8 warp-partial scalars
    } fold;
};

// ======================================================================
// Single fused persistent kernel, occupancy 3 (24 warps/SM):
//   phase 1: interleaved grid-stride (18 rows/warp) + 1600 tail rows
//            spread uniformly (442-443 rows/SM, 0.2% imbalance);
//            row n's mus parked in smem so row n+1's 8 LDG.128 fly
//            during the serial chain; 2-way split dist accumulator
//            halves the FMA dependency chain
//   grid sync (monotonic ticket; all blocks resident); global min via
//   atomicMin on float bits (true min -> deterministic, replay-safe reset)
//   phase 2: blocks 0..127 fold one float4 column each; rescale factors
//            registerized, all reductions warp-shuffle based (3 syncs)
// ======================================================================
__global__ __launch_bounds__(256, OCC)
void quant_fused(const float* __restrict__ imu,
                 const float* __restrict__ isg,
                 const float4* __restrict__ onst,   // row = 256 float4
                 float* __restrict__ out)           // [512 | 1 | 1 | 65536]
{
    __shared__ SmemU              u;                       // 20 KB
    __shared__ float4             s_a[8 * 32];             //  4 KB input stats [k*32+lane]
    __shared__ float              s_m[WARPS_PB];
    __shared__ float              s_Z[WARPS_PB];
    __shared__ unsigned long long s_epoch;
    __shared__ int                c_last;

    const int lane = threadIdx.x & 31;
    const int wid  = threadIdx.x >> 5;
    const int t    = threadIdx.x;
    const int gw   = blockIdx.x * WARPS_PB + wid;
    float* dists_out = out + LATENT + 2;

    // uniform tail distribution: warp gw is "heavy" (gets one tail row) iff
    // floor((gw+1)*1600/3552) > floor(gw*1600/3552); its tail row is
    // TAIL_BASE + floor(gw*1600/3552). Exactly 1600 heavy warps, 3-4/block.
    const int hr     = (gw * 1600) / NWARP;
    const int nrows  = BASE_ROWS + (((gw + 1) * 1600) / NWARP > hr);
    const int tailrw = TAIL_BASE + hr;

    // (0) FIRST: get the opening DRAM requests in flight (row k=0 is gw)
    float4 v[8];
    {
        const float4* p = onst + (size_t)gw * 256 + lane;
#pragma unroll
        for (int k = 0; k < 8; k++) v[k] = __ldcs(p + 32 * k);
    }

    // per-lane input-stats replica in shared (saves 32 regs):
    // entry [k*32+lane] covers float4 j=lane+32k -> d=2j (x:mu,y:sig), d=2j+1 (z:mu,w:sig)
    {
        int k2 = t >> 5, l2 = t & 31;
        int d0 = 2 * (l2 + 32 * k2);
        s_a[k2 * 32 + l2] = make_float4(imu[d0], isg[d0], imu[d0 + 1], isg[d0 + 1]);
    }
    __syncthreads();

    float m = CUDART_INF_F;
    float Z = 0.f;
    float q[16];
#pragma unroll
    for (int i = 0; i < 16; i++) q[i] = 0.f;

    // ---------------- phase 1: mu-stash pipelined streaming ----------------
    int row = gw;                          // row for iteration k: gw + k*NWARP, then tailrw
    for (int k = 0; k < nrows; k++) {
        // (1) consume v: 2-way split dist partials + park mus in the stash
        float sA = 0.f, sB = 0.f;
#pragma unroll
        for (int kk = 0; kk < 8; kk++) {
            float4 vk = v[kk];
            float4 ak = lds128v(&s_a[kk * 32 + lane]);
            u.stage[wid][kk][lane] = make_float2(vk.x, vk.z);
            float dx = vk.x - ak.x; sA = fmaf(dx, dx, sA);
            float dy = vk.y - ak.y; sB = fmaf(dy, dy, sB);
            float dz = vk.z - ak.z; sA = fmaf(dz, dz, sA);
            float dw = vk.w - ak.w; sB = fmaf(dw, dw, sB);
        }
        float s = sA + sB;

        // (2) v is dead: immediately launch next row's loads into it
        const int kn = k + 1;
        if (kn < nrows) {
            const int nrow = (kn < BASE_ROWS) ? gw + kn * NWARP : tailrw;
            const float4* pn = onst + (size_t)nrow * 256 + lane;
#pragma unroll
            for (int kk = 0; kk < 8; kk++) v[kk] = __ldcs(pn + 32 * kk);
        }

        // (3) serial chain runs while the 8 LDG.128 are in flight
#pragma unroll
        for (int o = 16; o > 0; o >>= 1)
            s += __shfl_xor_sync(0xffffffffu, s, o);

        if (lane == 0) dists_out[row] = s;

        // online softmin: weights exp(m - d_i), m = running min
        float w;
        if (s < m) {
            float f = __expf(s - m);       // first row: exp(-inf) = 0
            Z *= f;
#pragma unroll
            for (int i = 0; i < 16; i++) q[i] *= f;
            m = s;
            w = 1.f;
        } else {
            w = __expf(m - s);
        }
        Z += w;

        // (4) q-update from the stash (LDS, not the overwritten v)
#pragma unroll
        for (int kk = 0; kk < 8; kk++) {
            float2 mu = u.stage[wid][kk][lane];
            q[2 * kk]     = fmaf(w, mu.x, q[2 * kk]);
            q[2 * kk + 1] = fmaf(w, mu.y, q[2 * kk + 1]);
        }

        row = (kn < BASE_ROWS) ? gw + kn * NWARP : tailrw;
    }

    // ---- in-block fold of 8 warp states -> one (m, Z, q[512]) partial ----
    if (lane == 0) s_m[wid] = m;
    __syncthreads();                       // all warps done with u.stage

    float mB = s_m[0];
#pragma unroll
    for (int w2 = 1; w2 < WARPS_PB; w2++) mB = fminf(mB, s_m[w2]);

    const float fw = __expf(mB - m);       // <= 1
    if (lane == 0) s_Z[wid] = Z * fw;
#pragma unroll
    for (int k = 0; k < 8; k++) {
        int j = lane + 32 * k;
        u.fold.q[wid][2 * j]     = q[2 * k]     * fw;
        u.fold.q[wid][2 * j + 1] = q[2 * k + 1] * fw;
    }
    __syncthreads();

#pragma unroll
    for (int h = 0; h < 2; h++) {
        int c = t + 256 * h;
        float acc = 0.f;
#pragma unroll
        for (int w2 = 0; w2 < WARPS_PB; w2++) acc += u.fold.q[w2][c];
        g_blk_q[blockIdx.x * LATENT + c] = acc;
    }
    if (t == 0) {
        float zz = 0.f;
#pragma unroll
        for (int w2 = 0; w2 < WARPS_PB; w2++) zz += s_Z[w2];
        g_blk_Z[blockIdx.x] = zz;
        g_blk_m[blockIdx.x] = mB;
        // dists >= 0 -> float bits compare correctly as signed ints
        atomicMin(&g_gmin_bits, __float_as_int(mB));
    }

    // ---------------- grid sync (monotonic, graph-replay safe) ----------------
    __threadfence();
    if (t == 0) {
        unsigned long long ticket = atomicAdd(&g_sync, 1ULL);
        s_epoch = ticket / NBLK;           // same value for all blocks this launch
    }
    __syncthreads();

    if (blockIdx.x >= NCOL) return;        // non-combining blocks done

    if (t == 0) {
        const unsigned long long target = (s_epoch + 1ULL) * NBLK;
        while (ld_acq_u64(&g_sync) < target) { }
    }
    __syncthreads();
    __threadfence();                        // acquire partials from all blocks

    // ---------------- phase 2: column-parallel combine (L2-hot) ----------------
    // thread t handles partials b0=t and b1=t+256 (b1 valid iff t < NBLK-256);
    // rescale factors stay in registers, reductions are warp-shuffle based.
    const int j = blockIdx.x;              // float4 column 0..127
    const float M = __int_as_float(__ldcg(&g_gmin_bits));   // true global min
    const int b0 = t, b1 = t + 256;
    const bool has1 = (b1 < NBLK);
    const float4* q4 = (const float4*)g_blk_q;

    // issue both column loads early so L2 latency overlaps the Z reduction
    float4 x0 = q4[(size_t)b0 * NCOL + j];
    float4 x1 = has1 ? q4[(size_t)b1 * NCOL + j] : make_float4(0.f, 0.f, 0.f, 0.f);

    float fb0 = __expf(M - g_blk_m[b0]);
    float fb1 = has1 ? __expf(M - g_blk_m[b1]) : 0.f;

    float zv = g_blk_Z[b0] * fb0;
    if (has1) zv = fmaf(g_blk_Z[b1], fb1, zv);
#pragma unroll
    for (int o = 16; o > 0; o >>= 1)
        zv += __shfl_xor_sync(0xffffffffu, zv, o);
    if (lane == 0) u.fold.red[wid] = zv;

    // per-thread column fold, then warp-shuffle float4 reduce
    float4 acc;
    acc.x = fmaf(fb1, x1.x, fb0 * x0.x);
    acc.y = fmaf(fb1, x1.y, fb0 * x0.y);
    acc.z = fmaf(fb1, x1.z, fb0 * x0.z);
    acc.w = fmaf(fb1, x1.w, fb0 * x0.w);
#pragma unroll
    for (int o = 16; o > 0; o >>= 1) {
        acc.x += __shfl_xor_sync(0xffffffffu, acc.x, o);
        acc.y += __shfl_xor_sync(0xffffffffu, acc.y, o);
        acc.z += __shfl_xor_sync(0xffffffffu, acc.z, o);
        acc.w += __shfl_xor_sync(0xffffffffu, acc.w, o);
    }
    if (lane == 0) u.fold.cv[wid] = acc;
    __syncthreads();

    if (t == 0) {
        float Z2 = 0.f;
#pragma unroll
        for (int w2 = 0; w2 < WARPS_PB; w2++) Z2 += u.fold.red[w2];
        float4 r = u.fold.cv[0];
#pragma unroll
        for (int w2 = 1; w2 < WARPS_PB; w2++) {
            float4 x = u.fold.cv[w2];
            r.x += x.x; r.y += x.y; r.z += x.z; r.w += x.w;
        }
        ((float4*)out)[j] = make_float4(r.x / Z2, r.y / Z2, r.z / Z2, r.w / Z2);
    }

    // ---- last-block-done: losses from the finalized quantised vector ----
    __threadfence();
    if (t == 0) c_last = (atomicAdd(&g_ctr, 1u) == NCOL - 1);
    __syncthreads();

    if (c_last) {
        __threadfence();                   // acquire other blocks' out[] writes
        float e = 0.f;
        for (int d = t; d < LATENT; d += 256) {
            float qd   = __ldcg(&out[d]);  // bypass L1: other SMs wrote these
            float diff = qd - imu[d];
            e = fmaf(diff, diff, e);
        }
#pragma unroll
        for (int o = 16; o > 0; o >>= 1)
            e += __shfl_xor_sync(0xffffffffu, e, o);
        if (lane == 0) u.fold.red[wid] = e;
        __syncthreads();
        if (t == 0) {
            float ssum = 0.f;
#pragma unroll
            for (int w2 = 0; w2 < WARPS_PB; w2++) ssum += u.fold.red[w2];
            float loss = ssum / (float)LATENT;
            out[LATENT]     = loss;   // loss_enc
            out[LATENT + 1] = loss;   // loss_ref (stop_gradient => same value)
            g_ctr = 0;                // reset for next graph replay
            g_gmin_bits = INF_BITS;   // reset for next graph replay
        }
    }
}

// ======================================================================
extern "C" void kernel_launch(void* const* d_in, const int* in_sizes, int n_in,
                              void* d_out, int out_size)
{
    const float*  imu  = (const float*)d_in[0];   // input_mu  [512]
    const float*  isg  = (const float*)d_in[1];   // input_sig [512]
    const float4* onst = (const float4*)d_in[2];  // on_states [65536,512,2]
    float* out = (float*)d_out;                   // [512 | 1 | 1 | 65536]

    quant_fused<<<NBLK, 256>>>(imu, isg, onst, out);
}